// round 5
// baseline (speedup 1.0000x reference)
#include <cuda_runtime.h>
#include <cuda_bf16.h>

// Detection_23785528885376  (B=2, N=8192, C=32)
//
// Math collapse (R0): nn_idx[0]==0 always -> neighbor_feat = relu(f[b,0,:]).
// Per row: gamma = max_c( exp(f_c - f0_c) * f_c / max_c f ); out = gamma/||gamma||_2 per batch.
//
// R4 lesson: the two serialized global atomics (seq RMW + exch publish) cost
// ~600 cycles on the critical path at idle clocks. This version has ZERO
// atomics: seq comes from a plain load of last launch's value (launches are
// ordered), publish is one plain 64-bit store with flag+data packed in the
// same word. All warps poll & scale from registers (no smem gamma, one sync).

#define DET_N  8192
#define DET_C  32
#define BPB    32              // blocks per batch
#define BLOCK  512             // 16 warps
#define ROWS_PER_BLOCK 256
#define ROWS_PER_WARP  16
#define MAX_SLOTS 256

__device__ unsigned int       g_seq [MAX_SLOTS];   // last completed seq per block (zero-init)
__device__ unsigned long long g_slot[MAX_SLOTS];   // packed (seq<<32 | float bits)

__global__ void __launch_bounds__(BLOCK)
det_fused_kernel(const float* __restrict__ feat, float* __restrict__ out) {
    const int lane = threadIdx.x & 31;
    const int warp = threadIdx.x >> 5;        // 0..15
    const int seg  = lane >> 3;               // 0..3 : row within float4-load group
    const int sid  = lane & 7;                // 0..7 : 8 lanes per row, 4 channels each
    const int b    = blockIdx.x >> 5;         // BPB == 32
    const int block_row0 = blockIdx.x * ROWS_PER_BLOCK;
    const int warp_row0  = block_row0 + warp * ROWS_PER_WARP;

    __shared__ float sh_red[16];
    __shared__ unsigned int sh_tgt;

    // replay-safe target sequence: previous launch's value + 1 (plain load;
    // prior launch is fully ordered before this one; zero on first run)
    if (threadIdx.x == 0) sh_tgt = g_seq[blockIdx.x] + 1u;

    const float4* __restrict__ feat4 = (const float4*)feat;

    // relu'd row-0 feature of this batch; this lane's 4 channels
    float4 f0 = __ldg(&feat4[b * DET_N * (DET_C / 4) + sid]);
    f0.x = fmaxf(f0.x, 0.f); f0.y = fmaxf(f0.y, 0.f);
    f0.z = fmaxf(f0.z, 0.f); f0.w = fmaxf(f0.w, 0.f);

    // ---- preload 4x float4 (16 rows / warp, 4 rows per LDG.128) ----
    float4 t[4];
    #pragma unroll
    for (int j = 0; j < 4; j++)
        t[j] = feat4[(warp_row0 + j * 4) * (DET_C / 4) + lane];

    // ---- gamma per row; every lane keeps its segment's gamma in s_arr ----
    float s_arr[4];
    float local = 0.0f;                       // masked sum of gamma^2 (sid==0 lanes)
    #pragma unroll
    for (int j = 0; j < 4; j++) {
        float v0 = fmaxf(t[j].x, 0.f), v1 = fmaxf(t[j].y, 0.f);
        float v2 = fmaxf(t[j].z, 0.f), v3 = fmaxf(t[j].w, 0.f);
        float m = fmaxf(fmaxf(v0, v1), fmaxf(v2, v3));
        #pragma unroll
        for (int o = 1; o < 8; o <<= 1) m = fmaxf(m, __shfl_xor_sync(0xFFFFFFFFu, m, o));
        float rm = __fdividef(1.0f, m);
        float s0 = __expf(v0 - f0.x) * v0 * rm;
        float s1 = __expf(v1 - f0.y) * v1 * rm;
        float s2 = __expf(v2 - f0.z) * v2 * rm;
        float s3 = __expf(v3 - f0.w) * v3 * rm;
        float s = fmaxf(fmaxf(s0, s1), fmaxf(s2, s3));
        #pragma unroll
        for (int o = 1; o < 8; o <<= 1) s = fmaxf(s, __shfl_xor_sync(0xFFFFFFFFu, s, o));
        s_arr[j] = s;
        if (sid == 0) local += s * s;
    }
    // combine the 4 segment-leader lanes (0,8,16,24): 2 shfls
    local += __shfl_xor_sync(0xFFFFFFFFu, local, 8);
    local += __shfl_xor_sync(0xFFFFFFFFu, local, 16);
    if (lane == 0) sh_red[warp] = local;
    __syncthreads();

    // ---- publish (seq | partial): one plain 64-bit store, no atomics ----
    if (threadIdx.x == 0) {
        float q = sh_red[0];
        #pragma unroll
        for (int w = 1; w < 16; w++) q += sh_red[w];
        unsigned long long pk =
            ((unsigned long long)sh_tgt << 32) | (unsigned long long)__float_as_uint(q);
        *((volatile unsigned long long*)&g_slot[blockIdx.x]) = pk;
        g_seq[blockIdx.x] = sh_tgt;           // consumed by the NEXT launch only
    }

    // ---- every warp polls the 32 batch-peer slots and computes inv itself ----
    const unsigned target = sh_tgt;           // valid: written before the syncthreads
    volatile unsigned long long* slot =
        (volatile unsigned long long*)&g_slot[b * BPB + lane];
    unsigned long long v;
    bool ready;
    do {
        v = *slot;
        ready = (unsigned)(v >> 32) >= target;
    } while (!__all_sync(0xFFFFFFFFu, ready));

    float q = __uint_as_float((unsigned)(v & 0xFFFFFFFFu));
    #pragma unroll
    for (int o = 16; o; o >>= 1) q += __shfl_xor_sync(0xFFFFFFFFu, q, o);
    const float inv = rsqrtf(q);

    // ---- scale from registers; per-j store is 4 contiguous floats ----
    if (sid == 0) {
        #pragma unroll
        for (int j = 0; j < 4; j++)
            out[warp_row0 + j * 4 + seg] = s_arr[j] * inv;
    }
}

extern "C" void kernel_launch(void* const* d_in, const int* in_sizes, int n_in,
                              void* d_out, int out_size) {
    // inputs: [0] coords int32 (unused), [1] features f32 [B,N,C], [2] len_batch
    const float* feat = (const float*)d_in[1];
    const int B = in_sizes[1] / (DET_N * DET_C);
    det_fused_kernel<<<B * BPB, BLOCK>>>(feat, (float*)d_out);
}

// round 6
// speedup vs baseline: 1.6570x; 1.6570x over previous
#include <cuda_runtime.h>
#include <cuda_bf16.h>

// Detection_23785528885376  (B=2, N=8192, C=32)
//
// Math collapse (R0): nn_idx[0]==0 always -> neighbor_feat = relu(f[b,0,:]).
// Per row: gamma = max_c( exp(f_c - f0_c) * f_c / max_c f ); out = gamma/||gamma||_2 per batch.
//
// R5 lesson: 16 warps/block polling the slot array (1024 pollers) congested L2
// and delayed the publishes they were waiting on (+3us). R6 = R5's zero-atomic
// publish + R4's single-warp poll with smem broadcast of inv.

#define DET_N  8192
#define DET_C  32
#define BPB    32              // blocks per batch
#define BLOCK  512             // 16 warps
#define ROWS_PER_BLOCK 256
#define ROWS_PER_WARP  16
#define MAX_SLOTS 256

__device__ unsigned int       g_seq [MAX_SLOTS];   // last completed seq per block (zero-init)
__device__ unsigned long long g_slot[MAX_SLOTS];   // packed (seq<<32 | float bits)

__global__ void __launch_bounds__(BLOCK)
det_fused_kernel(const float* __restrict__ feat, float* __restrict__ out) {
    const int lane = threadIdx.x & 31;
    const int warp = threadIdx.x >> 5;        // 0..15
    const int seg  = lane >> 3;               // 0..3 : row within float4-load group
    const int sid  = lane & 7;                // 0..7 : 8 lanes per row, 4 channels each
    const int b    = blockIdx.x >> 5;         // BPB == 32
    const int block_row0 = blockIdx.x * ROWS_PER_BLOCK;
    const int warp_row0  = block_row0 + warp * ROWS_PER_WARP;

    __shared__ float sh_red[16];
    __shared__ float sh_inv;
    __shared__ unsigned int sh_tgt;

    // replay-safe target sequence: previous launch's value + 1 (plain load;
    // the prior launch is fully ordered before this one; zero on first run)
    if (threadIdx.x == 0) sh_tgt = g_seq[blockIdx.x] + 1u;

    const float4* __restrict__ feat4 = (const float4*)feat;

    // relu'd row-0 feature of this batch; this lane's 4 channels
    float4 f0 = __ldg(&feat4[b * DET_N * (DET_C / 4) + sid]);
    f0.x = fmaxf(f0.x, 0.f); f0.y = fmaxf(f0.y, 0.f);
    f0.z = fmaxf(f0.z, 0.f); f0.w = fmaxf(f0.w, 0.f);

    // ---- preload 4x float4 (16 rows / warp, 4 rows per LDG.128) ----
    float4 t[4];
    #pragma unroll
    for (int j = 0; j < 4; j++)
        t[j] = feat4[(warp_row0 + j * 4) * (DET_C / 4) + lane];

    // ---- gamma per row; lanes keep their segment's gamma in s_arr ----
    float s_arr[4];
    float local = 0.0f;                       // masked sum of gamma^2 (sid==0 lanes)
    #pragma unroll
    for (int j = 0; j < 4; j++) {
        float v0 = fmaxf(t[j].x, 0.f), v1 = fmaxf(t[j].y, 0.f);
        float v2 = fmaxf(t[j].z, 0.f), v3 = fmaxf(t[j].w, 0.f);
        float m = fmaxf(fmaxf(v0, v1), fmaxf(v2, v3));
        #pragma unroll
        for (int o = 1; o < 8; o <<= 1) m = fmaxf(m, __shfl_xor_sync(0xFFFFFFFFu, m, o));
        float rm = __fdividef(1.0f, m);
        float s0 = __expf(v0 - f0.x) * v0 * rm;
        float s1 = __expf(v1 - f0.y) * v1 * rm;
        float s2 = __expf(v2 - f0.z) * v2 * rm;
        float s3 = __expf(v3 - f0.w) * v3 * rm;
        float s = fmaxf(fmaxf(s0, s1), fmaxf(s2, s3));
        #pragma unroll
        for (int o = 1; o < 8; o <<= 1) s = fmaxf(s, __shfl_xor_sync(0xFFFFFFFFu, s, o));
        s_arr[j] = s;
        if (sid == 0) local += s * s;
    }
    // combine the 4 segment-leader lanes (0,8,16,24): 2 shfls
    local += __shfl_xor_sync(0xFFFFFFFFu, local, 8);
    local += __shfl_xor_sync(0xFFFFFFFFu, local, 16);
    if (lane == 0) sh_red[warp] = local;
    __syncthreads();

    // ---- publish (seq | partial): one plain 64-bit store, no atomics;
    //      then ONLY warp 0 polls the 32 batch-peer slots ----
    if (warp == 0) {
        const unsigned target = sh_tgt;
        if (lane == 0) {
            float q = sh_red[0];
            #pragma unroll
            for (int w = 1; w < 16; w++) q += sh_red[w];
            unsigned long long pk = ((unsigned long long)target << 32)
                                  | (unsigned long long)__float_as_uint(q);
            *((volatile unsigned long long*)&g_slot[blockIdx.x]) = pk;
            g_seq[blockIdx.x] = target;       // consumed by the NEXT launch only
        }
        volatile unsigned long long* slot =
            (volatile unsigned long long*)&g_slot[b * BPB + lane];
        unsigned long long v;
        bool ready;
        do {
            v = *slot;
            ready = (unsigned)(v >> 32) >= target;
        } while (!__all_sync(0xFFFFFFFFu, ready));

        float q = __uint_as_float((unsigned)(v & 0xFFFFFFFFu));
        #pragma unroll
        for (int o = 16; o; o >>= 1) q += __shfl_xor_sync(0xFFFFFFFFu, q, o);
        if (lane == 0) sh_inv = rsqrtf(q);
    }
    __syncthreads();
    const float inv = sh_inv;

    // ---- scale from registers; 4 contiguous floats per j ----
    if (sid == 0) {
        #pragma unroll
        for (int j = 0; j < 4; j++)
            out[warp_row0 + j * 4 + seg] = s_arr[j] * inv;
    }
}

extern "C" void kernel_launch(void* const* d_in, const int* in_sizes, int n_in,
                              void* d_out, int out_size) {
    // inputs: [0] coords int32 (unused), [1] features f32 [B,N,C], [2] len_batch
    const float* feat = (const float*)d_in[1];
    const int B = in_sizes[1] / (DET_N * DET_C);
    det_fused_kernel<<<B * BPB, BLOCK>>>(feat, (float*)d_out);
}